// round 13
// baseline (speedup 1.0000x reference)
#include <cuda_runtime.h>
#include <cuda_bf16.h>
#include <cstdint>

// ---------------------------------------------------------------------------
// AdaConv fused kernel set (round 12).
// Conv: thread = 4 oc x 1 row x 8 col-pairs; shifted-copy (A/B) smem rows so
// every f32x2 operand is an aligned LDS.64/128; weights hoisted per (o,ic,ky)
// as broadcast LDS.128+LDS.64; zero packing ALU in the hot loop; 16 warps/SM.
// ---------------------------------------------------------------------------

typedef unsigned long long ull;

__device__ __forceinline__ ull pack2(float lo, float hi) {
    ull r;
    asm("mov.b64 %0, {%1, %2};" : "=l"(r) : "f"(lo), "f"(hi));
    return r;
}
__device__ __forceinline__ void unpack2(ull v, float& lo, float& hi) {
    asm("mov.b64 {%0, %1}, %2;" : "=f"(lo), "=f"(hi) : "l"(v));
}
__device__ __forceinline__ void fma2(ull& acc, ull a, ull b) {
    asm("fma.rn.f32x2 %0, %1, %2, %0;" : "+l"(acc) : "l"(a), "l"(b));
}

// ------------------------- scratch (device globals) ------------------------
__device__ float g_colT[8 * 9 * 2048];   // im2col of style: [n][t][k]
__device__ float g_spool[8 * 512];       // avg-pooled style
__device__ float g_dw[8 * 4096 * 9];     // depthwise kernels [n][oc][t]
__device__ float g_pwkn[8 * 4096];       // pointwise kernels [n][c*8+j]
__device__ float g_pwbias[8 * 512];      // pointwise bias
__device__ float g_mean[8 * 512];
__device__ float g_rstd[8 * 512];

// ------------------------- K1: im2col + avg pool ---------------------------
__global__ void k_prep1(const float* __restrict__ style) {
    int idx = blockIdx.x * blockDim.x + threadIdx.x;
    const int COLT = 8 * 9 * 2048;
    if (idx < COLT) {
        int n = idx / (9 * 2048);
        int r = idx % (9 * 2048);
        int t = r / 2048;
        int k = r % 2048;
        int c = k >> 2, dy = (k >> 1) & 1, dx = k & 1;
        int ty = t / 3, tx = t % 3;
        g_colT[idx] = style[((n * 512 + c) * 4 + (ty + dy)) * 4 + (tx + dx)];
    } else if (idx < COLT + 4096) {
        int j = idx - COLT;
        const float* p = style + (size_t)j * 16;
        float s = 0.f;
#pragma unroll
        for (int q = 0; q < 16; q++) s += p[q];
        g_spool[j] = s * (1.f / 16.f);
    }
}

// ------------------------- K2: pointwise heads -----------------------------
__global__ void k_prep2(const float* __restrict__ pk_w, const float* __restrict__ pk_b,
                        const float* __restrict__ pb_w, const float* __restrict__ pb_b) {
    int idx = blockIdx.x * blockDim.x + threadIdx.x;
    if (idx < 32768) {
        int n = idx >> 12, oc = idx & 4095;
        const float4* w = (const float4*)(pk_w + (size_t)oc * 512);
        const float4* s = (const float4*)(g_spool + n * 512);
        float acc = pk_b[oc];
#pragma unroll 4
        for (int q = 0; q < 128; q++) {
            float4 a = w[q], b = s[q];
            acc += a.x * b.x + a.y * b.y + a.z * b.z + a.w * b.w;
        }
        g_pwkn[idx] = acc;
    } else if (idx < 32768 + 4096) {
        int j = idx - 32768;
        int n = j >> 9, c = j & 511;
        const float4* w = (const float4*)(pb_w + (size_t)c * 512);
        const float4* s = (const float4*)(g_spool + n * 512);
        float acc = pb_b[c];
#pragma unroll 4
        for (int q = 0; q < 128; q++) {
            float4 a = w[q], b = s[q];
            acc += a.x * b.x + a.y * b.y + a.z * b.z + a.w * b.w;
        }
        g_pwbias[j] = acc;
    }
}

// ------------------------- K3: dw GEMM (4096x72, k=2048) -------------------
__global__ void __launch_bounds__(288) k_dw(const float* __restrict__ dw_w,
                                            const float* __restrict__ dw_b) {
    __shared__ float s_col[9][516];
    int n = blockIdx.x >> 7;
    int ocb = blockIdx.x & 127;
    int tid = threadIdx.x;
    int oc_l = tid / 9, t = tid % 9;
    int oc = ocb * 32 + oc_l;
    const float* wrow = dw_w + (size_t)oc * 2048;
    ull acc = 0ULL;
    for (int kc = 0; kc < 4; kc++) {
        __syncthreads();
        for (int j = tid; j < 9 * 512; j += 288) {
            int tt = j >> 9, kk = j & 511;
            s_col[tt][kk] = g_colT[(n * 9 + tt) * 2048 + kc * 512 + kk];
        }
        __syncthreads();
        const float* wc = wrow + kc * 512;
#pragma unroll 4
        for (int k = 0; k < 512; k += 4) {
            longlong2 w2 = *(const longlong2*)(wc + k);
            longlong2 c2 = *(const longlong2*)(&s_col[t][k]);
            fma2(acc, (ull)w2.x, (ull)c2.x);
            fma2(acc, (ull)w2.y, (ull)c2.y);
        }
    }
    float lo, hi;
    unpack2(acc, lo, hi);
    g_dw[((size_t)n * 4096 + oc) * 9 + t] = lo + hi + dw_b[oc];
}

// ------------------------- K4: instance-norm stats -------------------------
__global__ void __launch_bounds__(256) k_stats(const float* __restrict__ pred) {
    int bc = blockIdx.x;  // n*512+c
    const float4* p = (const float4*)(pred + (size_t)bc * 16384);
    int tid = threadIdx.x;
    float s = 0.f, ss = 0.f;
#pragma unroll
    for (int k = 0; k < 16; k++) {
        float4 v = p[tid + k * 256];
        s += v.x + v.y + v.z + v.w;
        ss += v.x * v.x + v.y * v.y + v.z * v.z + v.w * v.w;
    }
#pragma unroll
    for (int o = 16; o; o >>= 1) {
        s += __shfl_xor_sync(~0u, s, o);
        ss += __shfl_xor_sync(~0u, ss, o);
    }
    __shared__ float ws[8], wss[8];
    if ((tid & 31) == 0) { ws[tid >> 5] = s; wss[tid >> 5] = ss; }
    __syncthreads();
    if (tid == 0) {
        float S = 0.f, SS = 0.f;
#pragma unroll
        for (int w = 0; w < 8; w++) { S += ws[w]; SS += wss[w]; }
        float mean = S * (1.f / 16384.f);
        float var = (SS - S * mean) * (1.f / 16383.f);  // ddof=1
        g_mean[bc] = mean;
        g_rstd[bc] = rsqrtf(var + 1e-5f);
    }
}

// ------------------------- K5: main grouped conv ---------------------------
// grid: (16 = 2 oc-halves x 8 y-tiles, 512 (n,g)), block 128 (8q x 16row).
// Tile: 128 cols x 16 rows x 4 oc. Thread: 4 oc x 1 row x 8 pairs.
// Input row layout: A[a]=x[a-1] (a=0..129) at [0], B[j]=x[j] (j=0..128) at
// [132]; row stride 264 floats. Taps of pair c: A[c], B[c], A[c+2] (aligned).
struct ConvSmem {
    float in[18][264];       // one input channel, A + shifted B
    float2 wq[4][8][3][4];   // [o][i][ky][kx pad4]: (w,w) duplicated
    float dw[64][9];         // group dw rows [j*8+i][t]
    float kn[32];            // pwkn for this half's 4 oc x 8 j
    float bias[4];
};

__global__ void __launch_bounds__(128, 4) k_conv(const float* __restrict__ pred,
                                                 float* __restrict__ out) {
    __shared__ ConvSmem S;

    int gb = blockIdx.y;  // n*64+g
    int n = gb >> 6, g = gb & 63;
    int oh = blockIdx.x & 1;        // oc half: oc = oh*4 + o
    int y0 = (blockIdx.x >> 1) * 16;
    int tid = threadIdx.x;
    int cbase = n * 512 + g * 8;

    // stage 1: group dw + this half's pwkn
    for (int idx = tid; idx < 576; idx += 128) {
        int t = idx % 9;
        int r = idx / 9;  // j*8+i
        S.dw[r][t] = g_dw[((size_t)n * 4096 + (g * 8 + (r >> 3)) * 8 + (r & 7)) * 9 + t];
    }
    if (tid < 32)
        S.kn[tid] = g_pwkn[n * 4096 + (g * 8 + oh * 4 + (tid >> 3)) * 8 + (tid & 7)];
    __syncthreads();

    // stage 2: fuse W_eff * rstd_i into wq
    for (int idx = tid; idx < 288; idx += 128) {
        int t = idx % 9;
        int r = idx / 9;
        int i = r & 7;
        int o = r >> 3;
        float acc = 0.f;
#pragma unroll
        for (int j = 0; j < 8; j++) acc += S.kn[o * 8 + j] * S.dw[j * 8 + i][t];
        float w = acc * g_rstd[cbase + i];
        S.wq[o][i][t / 3][t % 3] = make_float2(w, w);
    }
    __syncthreads();

    // stage 3: bias with mean fold (this half's 4 oc)
    if (tid < 4) {
        int o = tid;
        float b = g_pwbias[cbase + oh * 4 + o];
#pragma unroll
        for (int i = 0; i < 8; i++) {
            float m = g_mean[cbase + i];
            float sw = 0.f;
#pragma unroll
            for (int ky = 0; ky < 3; ky++)
#pragma unroll
                for (int kx = 0; kx < 3; kx++) sw += S.wq[o][i][ky][kx].x;
            b -= sw * m;
        }
        S.bias[o] = b;
    }
    __syncthreads();

    int q = tid & 7;        // col quarter: cols 16q .. 16q+15
    int row = tid >> 3;     // output row 0..15 (tile-local)
    const int c0 = q * 16;

    // fill-x reflect precompute: thread covers rx=tid; tid<2 also rx=128+tid
    int gx0 = (tid == 0) ? 1 : tid - 1;        // x coord for A[rx=tid]
    int gx2 = (tid == 0) ? 127 : 126;          // x coord for rx=128+tid

    // acc init = packed bias
    ull acc[4][8];
#pragma unroll
    for (int o = 0; o < 4; o++) {
        float b = S.bias[o];
        ull bb = pack2(b, b);
#pragma unroll
        for (int p = 0; p < 8; p++) acc[o][p] = bb;
    }

#pragma unroll 1
    for (int ic = 0; ic < 8; ic++) {
        // ---- fill A + shifted copy B for this input channel ----
        const float* plane = pred + (size_t)(cbase + ic) * 16384;
#pragma unroll 1
        for (int ry = 0; ry < 18; ry++) {
            int gy = y0 - 1 + ry;
            gy = gy < 0 ? -gy : (gy > 127 ? 254 - gy : gy);
            float v = plane[gy * 128 + gx0];
            S.in[ry][tid] = v;                        // A[tid]
            if (tid >= 1) S.in[ry][132 + tid - 1] = v;  // B[tid-1]
            if (tid < 2) {
                float v2 = plane[gy * 128 + gx2];
                S.in[ry][128 + tid] = v2;             // A[128], A[129]
                S.in[ry][132 + 127 + tid] = v2;       // B[127], B[128]
            }
        }
        __syncthreads();

        // ---- compute ----
        int icb = ic;  // runtime channel index into wq
#pragma unroll
        for (int ky = 0; ky < 3; ky++) {
            const float* Ar = &S.in[row + ky][c0];
            ulonglong2 a01 = *(const ulonglong2*)(Ar + 0);
            ulonglong2 a23 = *(const ulonglong2*)(Ar + 4);
            ulonglong2 a45 = *(const ulonglong2*)(Ar + 8);
            ulonglong2 a67 = *(const ulonglong2*)(Ar + 12);
            ull A8 = *(const ull*)(Ar + 16);
            const float* Br = Ar + 132;
            ulonglong2 b01 = *(const ulonglong2*)(Br + 0);
            ulonglong2 b23 = *(const ulonglong2*)(Br + 4);
            ulonglong2 b45 = *(const ulonglong2*)(Br + 8);
            ulonglong2 b67 = *(const ulonglong2*)(Br + 12);
            ull A[9] = {(ull)a01.x, (ull)a01.y, (ull)a23.x, (ull)a23.y,
                        (ull)a45.x, (ull)a45.y, (ull)a67.x, (ull)a67.y, A8};
            ull B[8] = {(ull)b01.x, (ull)b01.y, (ull)b23.x, (ull)b23.y,
                        (ull)b45.x, (ull)b45.y, (ull)b67.x, (ull)b67.y};
#pragma unroll
            for (int o = 0; o < 4; o++) {
                ulonglong2 w01 = *(const ulonglong2*)&S.wq[o][icb][ky][0];
                ull w2v = *(const ull*)&S.wq[o][icb][ky][2];
#pragma unroll
                for (int p = 0; p < 8; p++) {
                    fma2(acc[o][p], (ull)w01.x, A[p]);
                    fma2(acc[o][p], (ull)w01.y, B[p]);
                    fma2(acc[o][p], w2v, A[p + 1]);
                }
            }
        }
        __syncthreads();
    }

    // epilogue: direct 8B stores (bias already folded into acc init)
#pragma unroll
    for (int o = 0; o < 4; o++) {
        float* ob = out + (size_t)(cbase + oh * 4 + o) * 16384 +
                    (size_t)(y0 + row) * 128 + c0;
#pragma unroll
        for (int p = 0; p < 8; p++) *(ull*)(ob + 2 * p) = acc[o][p];
    }
}

// ------------------------- launch ------------------------------------------
extern "C" void kernel_launch(void* const* d_in, const int* in_sizes, int n_in,
                              void* d_out, int out_size) {
    const float* style = (const float*)d_in[0];
    const float* predicted = (const float*)d_in[1];
    const float* dw_w = (const float*)d_in[2];
    const float* dw_b = (const float*)d_in[3];
    const float* pk_w = (const float*)d_in[4];
    const float* pk_b = (const float*)d_in[5];
    const float* pb_w = (const float*)d_in[6];
    const float* pb_b = (const float*)d_in[7];
    float* out = (float*)d_out;

    (void)in_sizes; (void)n_in; (void)out_size;

    k_prep1<<<(147456 + 4096 + 255) / 256, 256>>>(style);
    k_prep2<<<(32768 + 4096 + 255) / 256, 256>>>(pk_w, pk_b, pb_w, pb_b);
    k_dw<<<1024, 288>>>(dw_w, dw_b);
    k_stats<<<4096, 256>>>(predicted);
    dim3 cgrid(16, 512);
    k_conv<<<cgrid, 128>>>(predicted, out);
}

// round 16
// speedup vs baseline: 2.1777x; 2.1777x over previous
#include <cuda_runtime.h>
#include <cuda_bf16.h>
#include <cstdint>

// ---------------------------------------------------------------------------
// AdaConv fused kernel set (round 14).
// Change vs best (R4/721us): k_dw redundant row loads fixed by cooperative
// smem staging (was ~240us LSU-bound on 9x-duplicated LDG/LDS).
// Conv restored verbatim from the 721us best. Launch order puts k_dw 4th so
// ncu captures it.
// ---------------------------------------------------------------------------

typedef unsigned long long ull;

__device__ __forceinline__ ull pack2(float lo, float hi) {
    ull r;
    asm("mov.b64 %0, {%1, %2};" : "=l"(r) : "f"(lo), "f"(hi));
    return r;
}
__device__ __forceinline__ void unpack2(ull v, float& lo, float& hi) {
    asm("mov.b64 {%0, %1}, %2;" : "=f"(lo), "=f"(hi) : "l"(v));
}
__device__ __forceinline__ void fma2(ull& acc, ull a, ull b) {
    asm("fma.rn.f32x2 %0, %1, %2, %0;" : "+l"(acc) : "l"(a), "l"(b));
}

// ------------------------- scratch (device globals) ------------------------
__device__ float g_colT[8 * 9 * 2048];   // im2col of style: [n][t][k]
__device__ float g_spool[8 * 512];       // avg-pooled style
__device__ float g_dw[8 * 4096 * 9];     // depthwise kernels [n][oc][t]
__device__ float g_pwkn[8 * 4096];       // pointwise kernels [n][c*8+j]
__device__ float g_pwbias[8 * 512];      // pointwise bias
__device__ float g_mean[8 * 512];
__device__ float g_rstd[8 * 512];

// ------------------------- K1: instance-norm stats -------------------------
__global__ void __launch_bounds__(256) k_stats(const float* __restrict__ pred) {
    int bc = blockIdx.x;  // n*512+c
    const float4* p = (const float4*)(pred + (size_t)bc * 16384);
    int tid = threadIdx.x;
    float s = 0.f, ss = 0.f;
#pragma unroll
    for (int k = 0; k < 16; k++) {
        float4 v = p[tid + k * 256];
        s += v.x + v.y + v.z + v.w;
        ss += v.x * v.x + v.y * v.y + v.z * v.z + v.w * v.w;
    }
#pragma unroll
    for (int o = 16; o; o >>= 1) {
        s += __shfl_xor_sync(~0u, s, o);
        ss += __shfl_xor_sync(~0u, ss, o);
    }
    __shared__ float ws[8], wss[8];
    if ((tid & 31) == 0) { ws[tid >> 5] = s; wss[tid >> 5] = ss; }
    __syncthreads();
    if (tid == 0) {
        float S = 0.f, SS = 0.f;
#pragma unroll
        for (int w = 0; w < 8; w++) { S += ws[w]; SS += wss[w]; }
        float mean = S * (1.f / 16384.f);
        float var = (SS - S * mean) * (1.f / 16383.f);  // ddof=1
        g_mean[bc] = mean;
        g_rstd[bc] = rsqrtf(var + 1e-5f);
    }
}

// ------------------------- K2: im2col + avg pool ---------------------------
__global__ void k_prep1(const float* __restrict__ style) {
    int idx = blockIdx.x * blockDim.x + threadIdx.x;
    const int COLT = 8 * 9 * 2048;
    if (idx < COLT) {
        int n = idx / (9 * 2048);
        int r = idx % (9 * 2048);
        int t = r / 2048;
        int k = r % 2048;
        int c = k >> 2, dy = (k >> 1) & 1, dx = k & 1;
        int ty = t / 3, tx = t % 3;
        g_colT[idx] = style[((n * 512 + c) * 4 + (ty + dy)) * 4 + (tx + dx)];
    } else if (idx < COLT + 4096) {
        int j = idx - COLT;
        const float* p = style + (size_t)j * 16;
        float s = 0.f;
#pragma unroll
        for (int q = 0; q < 16; q++) s += p[q];
        g_spool[j] = s * (1.f / 16.f);
    }
}

// ------------------------- K3: pointwise heads -----------------------------
__global__ void k_prep2(const float* __restrict__ pk_w, const float* __restrict__ pk_b,
                        const float* __restrict__ pb_w, const float* __restrict__ pb_b) {
    int idx = blockIdx.x * blockDim.x + threadIdx.x;
    if (idx < 32768) {
        int n = idx >> 12, oc = idx & 4095;
        const float4* w = (const float4*)(pk_w + (size_t)oc * 512);
        const float4* s = (const float4*)(g_spool + n * 512);
        float acc = pk_b[oc];
#pragma unroll 4
        for (int q = 0; q < 128; q++) {
            float4 a = w[q], b = s[q];
            acc += a.x * b.x + a.y * b.y + a.z * b.z + a.w * b.w;
        }
        g_pwkn[idx] = acc;
    } else if (idx < 32768 + 4096) {
        int j = idx - 32768;
        int n = j >> 9, c = j & 511;
        const float4* w = (const float4*)(pb_w + (size_t)c * 512);
        const float4* s = (const float4*)(g_spool + n * 512);
        float acc = pb_b[c];
#pragma unroll 4
        for (int q = 0; q < 128; q++) {
            float4 a = w[q], b = s[q];
            acc += a.x * b.x + a.y * b.y + a.z * b.z + a.w * b.w;
        }
        g_pwbias[j] = acc;
    }
}

// ------------------------- K4: dw GEMM (4096x72, k=2048) -------------------
// block: 288 threads = 32 oc x 9 t. BOTH operands staged in shared per
// 128-k chunk: w chunk loaded once (coalesced) instead of 9x per row.
__global__ void __launch_bounds__(288) k_dw(const float* __restrict__ dw_w,
                                            const float* __restrict__ dw_b) {
    __shared__ float s_col[9][132];   // col chunk [t][k], padded stride
    __shared__ float s_w[32][132];    // w chunk [oc_l][k], padded stride
    int n = blockIdx.x >> 7;
    int ocb = blockIdx.x & 127;
    int tid = threadIdx.x;
    int oc_l = tid / 9, t = tid % 9;
    int oc = ocb * 32 + oc_l;
    ull acc = 0ULL;
#pragma unroll 1
    for (int kc = 0; kc < 16; kc++) {
        __syncthreads();
        // stage col chunk: 9 x 128 floats
        for (int j = tid; j < 9 * 128; j += 288) {
            int tt = j >> 7, kk = j & 127;
            s_col[tt][kk] = g_colT[(n * 9 + tt) * 2048 + kc * 128 + kk];
        }
        // stage w chunk: 32 x 128 floats as float4 (each row loaded ONCE)
        for (int j = tid; j < 32 * 32; j += 288) {
            int r = j >> 5, c4 = j & 31;
            float4 v = *(const float4*)(dw_w + (size_t)(ocb * 32 + r) * 2048 +
                                        kc * 128 + c4 * 4);
            *(float4*)&s_w[r][c4 * 4] = v;
        }
        __syncthreads();
#pragma unroll
        for (int k = 0; k < 128; k += 4) {
            longlong2 w2 = *(const longlong2*)&s_w[oc_l][k];
            longlong2 c2 = *(const longlong2*)&s_col[t][k];
            fma2(acc, (ull)w2.x, (ull)c2.x);
            fma2(acc, (ull)w2.y, (ull)c2.y);
        }
    }
    float lo, hi;
    unpack2(acc, lo, hi);
    g_dw[((size_t)n * 4096 + oc) * 9 + t] = lo + hi + dw_b[oc];
}

// ------------------------- K5: main grouped conv (R4 verbatim) -------------
// grid: (16 tiles [2x x 8y], 512 (n,g)), block 128 threads.
// Tile: 64 x 16 output, 8 in-ch, 8 out-ch computed as 2 passes of 4.
__global__ void __launch_bounds__(128) k_conv(const float* __restrict__ pred,
                                              float* __restrict__ out) {
    __shared__ float s_in[8][18][68];
    __shared__ float s_dw[64][9];
    __shared__ float s_kn[64];
    __shared__ float2 s_w2[8][8][9];
    __shared__ float s_bias[8];

    int gb = blockIdx.y;  // n*64+g
    int n = gb >> 6, g = gb & 63;
    int x0 = (blockIdx.x & 1) * 64;
    int y0 = (blockIdx.x >> 1) * 16;
    int tid = threadIdx.x;
    int cbase = n * 512 + g * 8;

    // stage 1: load group dw + pwkn
    for (int idx = tid; idx < 576; idx += 128) {
        int t = idx % 9;
        int r = idx / 9;  // j*8+i
        s_dw[r][t] = g_dw[((size_t)n * 4096 + (g * 8 + (r >> 3)) * 8 + (r & 7)) * 9 + t];
    }
    if (tid < 64)
        s_kn[tid] = g_pwkn[n * 4096 + (g * 8 + (tid >> 3)) * 8 + (tid & 7)];
    __syncthreads();

    // stage 2: fuse into W_eff * rstd_i; load input tile (independent)
    for (int idx = tid; idx < 576; idx += 128) {
        int t = idx % 9;
        int r = idx / 9;
        int i = r & 7;
        int o = r >> 3;
        float acc = 0.f;
#pragma unroll
        for (int j = 0; j < 8; j++) acc += s_kn[o * 8 + j] * s_dw[j * 8 + i][t];
        float w = acc * g_rstd[cbase + i];
        s_w2[o][i][t] = make_float2(w, w);
    }
    const float* pbase = pred + (size_t)cbase * 16384;
    for (int idx = tid; idx < 8 * 18 * 66; idx += 128) {
        int rx = idx % 66;
        int r = idx / 66;
        int ry = r % 18;
        int i = r / 18;
        int gy = y0 - 1 + ry;
        gy = gy < 0 ? -gy : (gy > 127 ? 254 - gy : gy);
        int gx = x0 - 1 + rx;
        gx = gx < 0 ? -gx : (gx > 127 ? 254 - gx : gx);
        s_in[i][ry][rx] = pbase[(size_t)i * 16384 + gy * 128 + gx];
    }
    __syncthreads();

    // stage 3: bias with mean fold
    if (tid < 8) {
        int o = tid;
        float b = g_pwbias[cbase + o];
#pragma unroll
        for (int i = 0; i < 8; i++) {
            float m = g_mean[cbase + i];
            float sw = 0.f;
#pragma unroll
            for (int t = 0; t < 9; t++) sw += s_w2[o][i][t].x;
            b -= sw * m;
        }
        s_bias[o] = b;
    }
    __syncthreads();

    int px = tid & 7;   // x octet (8 output pixels)
    int py = tid >> 3;  // output row
    float* obase = out + (size_t)cbase * 16384 + (size_t)(y0 + py) * 128 + x0 + px * 8;

#pragma unroll 1
    for (int oh = 0; oh < 2; oh++) {
        ull acc[4][4];
#pragma unroll
        for (int o = 0; o < 4; o++)
#pragma unroll
            for (int q = 0; q < 4; q++) acc[o][q] = 0ULL;

#pragma unroll 1
        for (int i = 0; i < 8; i++) {
#pragma unroll
            for (int ky = 0; ky < 3; ky++) {
                const float* rp = &s_in[i][py + ky][px * 8];
                float4 a = *(const float4*)rp;
                float4 b = *(const float4*)(rp + 4);
                float v8 = rp[8], v9 = rp[9];
                ull P[9];
                P[0] = pack2(a.x, a.y);
                P[1] = pack2(a.y, a.z);
                P[2] = pack2(a.z, a.w);
                P[3] = pack2(a.w, b.x);
                P[4] = pack2(b.x, b.y);
                P[5] = pack2(b.y, b.z);
                P[6] = pack2(b.z, b.w);
                P[7] = pack2(b.w, v8);
                P[8] = pack2(v8, v9);
#pragma unroll
                for (int kx = 0; kx < 3; kx++) {
#pragma unroll
                    for (int o = 0; o < 4; o++) {
                        ull w2 = *(const ull*)&s_w2[oh * 4 + o][i][ky * 3 + kx];
                        fma2(acc[o][0], w2, P[kx + 0]);
                        fma2(acc[o][1], w2, P[kx + 2]);
                        fma2(acc[o][2], w2, P[kx + 4]);
                        fma2(acc[o][3], w2, P[kx + 6]);
                    }
                }
            }
        }

#pragma unroll
        for (int o = 0; o < 4; o++) {
            float b = s_bias[oh * 4 + o];
            float u0, u1, u2, u3, u4, u5, u6, u7;
            unpack2(acc[o][0], u0, u1);
            unpack2(acc[o][1], u2, u3);
            unpack2(acc[o][2], u4, u5);
            unpack2(acc[o][3], u6, u7);
            float4 lo = make_float4(u0 + b, u1 + b, u2 + b, u3 + b);
            float4 hi = make_float4(u4 + b, u5 + b, u6 + b, u7 + b);
            float* op = obase + (size_t)(oh * 4 + o) * 16384;
            *(float4*)op = lo;
            *(float4*)(op + 4) = hi;
        }
    }
}

// ------------------------- launch ------------------------------------------
extern "C" void kernel_launch(void* const* d_in, const int* in_sizes, int n_in,
                              void* d_out, int out_size) {
    const float* style = (const float*)d_in[0];
    const float* predicted = (const float*)d_in[1];
    const float* dw_w = (const float*)d_in[2];
    const float* dw_b = (const float*)d_in[3];
    const float* pk_w = (const float*)d_in[4];
    const float* pk_b = (const float*)d_in[5];
    const float* pb_w = (const float*)d_in[6];
    const float* pb_b = (const float*)d_in[7];
    float* out = (float*)d_out;

    (void)in_sizes; (void)n_in; (void)out_size;

    // order chosen so launch #4 (ncu capture slot) = the new k_dw
    k_stats<<<4096, 256>>>(predicted);
    k_prep1<<<(147456 + 4096 + 255) / 256, 256>>>(style);
    k_prep2<<<(32768 + 4096 + 255) / 256, 256>>>(pk_w, pk_b, pb_w, pb_b);
    k_dw<<<1024, 288>>>(dw_w, dw_b);
    dim3 cgrid(16, 512);
    k_conv<<<cgrid, 128>>>(predicted, out);
}